// round 8
// baseline (speedup 1.0000x reference)
#include <cuda_runtime.h>
#include <cuda_bf16.h>
#include <cuda_fp8.h>
#include <cstdint>

// Shape (fixed): x[4,2048,4096] -> M=8192, K=4096; W[4096,4096] -> N=4096.
static constexpr int MDIM = 8192;
static constexpr int NDIM = 4096;
static constexpr int KDIM = 4096;

// fp8 tiles: BK = 128 fp8 bytes per mainloop iteration
static constexpr int BM = 128, BN = 128, BK = 128;
static constexpr int NSTAGE = 3;
static constexpr int A_STAGE = BM * BK;                // 16384 B
static constexpr int STAGE_BYTES = 2 * A_STAGE;        // 32768 B (A + B)
static constexpr int SMEM_SIZE = NSTAGE * STAGE_BYTES; // 96 KB -> 2 CTAs/SM (192KB)
static constexpr int NIT = KDIM / BK;                  // 32
static constexpr int NTHREADS = 512;                   // 16 warps, 4x4 warp grid

// Scratch (allocation-free rule: __device__ globals)
__device__ uint8_t g_A[(size_t)MDIM * KDIM];   // 32 MB quantized activations (e4m3)
__device__ uint8_t g_B[(size_t)NDIM * KDIM];   // 16 MB quantized weights (e4m3)
__device__ unsigned g_amax_bits;

// ---------------- helpers ----------------
__device__ __forceinline__ uint32_t smem_u32(const void* p) {
    uint32_t a;
    asm("{ .reg .u64 t; cvta.to.shared.u64 t, %1; cvt.u32.u64 %0, t; }" : "=r"(a) : "l"(p));
    return a;
}
__device__ __forceinline__ void cp16(uint32_t dst, const void* src) {
    asm volatile("cp.async.cg.shared.global [%0], [%1], 16;" :: "r"(dst), "l"(src));
}
__device__ __forceinline__ void cp_commit() { asm volatile("cp.async.commit_group;" ::: "memory"); }
__device__ __forceinline__ void cp_wait1()  { asm volatile("cp.async.wait_group 1;" ::: "memory"); }

__device__ __forceinline__ void ldsm_x4(uint32_t& r0, uint32_t& r1, uint32_t& r2, uint32_t& r3,
                                        uint32_t addr) {
    asm volatile("ldmatrix.sync.aligned.m8n8.x4.shared.b16 {%0,%1,%2,%3}, [%4];"
                 : "=r"(r0), "=r"(r1), "=r"(r2), "=r"(r3) : "r"(addr));
}
// fp8 e4m3 MMA, fp32 accum, K=32 per instruction.
__device__ __forceinline__ void mma_fp8(float* c, const uint32_t* a, uint32_t b0, uint32_t b1) {
    asm volatile(
        "mma.sync.aligned.m16n8k32.row.col.f32.e4m3.e4m3.f32 "
        "{%0,%1,%2,%3}, {%4,%5,%6,%7}, {%8,%9}, {%0,%1,%2,%3};"
        : "+f"(c[0]), "+f"(c[1]), "+f"(c[2]), "+f"(c[3])
        : "r"(a[0]), "r"(a[1]), "r"(a[2]), "r"(a[3]), "r"(b0), "r"(b1));
}

// ---------------- quantization kernels ----------------
__global__ void k_reset() { g_amax_bits = 0u; }

__device__ __forceinline__ float max4(float4 v) {
    return fmaxf(fmaxf(fabsf(v.x), fabsf(v.y)), fmaxf(fabsf(v.z), fabsf(v.w)));
}

__global__ void k_amax(const float4* __restrict__ x, int n4) {
    const int stride = gridDim.x * blockDim.x;
    int i = blockIdx.x * blockDim.x + threadIdx.x;
    float m0 = 0.f, m1 = 0.f, m2 = 0.f, m3 = 0.f;
    for (; i + 3 * stride < n4; i += 4 * stride) {
        float4 a = x[i], b = x[i + stride], c = x[i + 2 * stride], d = x[i + 3 * stride];
        m0 = fmaxf(m0, max4(a));
        m1 = fmaxf(m1, max4(b));
        m2 = fmaxf(m2, max4(c));
        m3 = fmaxf(m3, max4(d));
    }
    for (; i < n4; i += stride) m0 = fmaxf(m0, max4(x[i]));
    float m = fmaxf(fmaxf(m0, m1), fmaxf(m2, m3));
#pragma unroll
    for (int o = 16; o; o >>= 1) m = fmaxf(m, __shfl_xor_sync(0xffffffffu, m, o));
    __shared__ float red[32];
    if ((threadIdx.x & 31) == 0) red[threadIdx.x >> 5] = m;
    __syncthreads();
    if (threadIdx.x < 32) {
        m = (threadIdx.x < (blockDim.x >> 5)) ? red[threadIdx.x] : 0.f;
#pragma unroll
        for (int o = 16; o; o >>= 1) m = fmaxf(m, __shfl_xor_sync(0xffffffffu, m, o));
        if (threadIdx.x == 0) atomicMax(&g_amax_bits, __float_as_uint(m));
    }
}

// Correctly-rounded x/s via one FMA refinement (matches reference's IEEE division)
__device__ __forceinline__ float div_rn(float x, float s, float r) {
    float q0 = x * r;
    return fmaf(fmaf(-s, q0, x), r, q0);
}
__device__ __forceinline__ uint8_t e4m3_byte(float v) {
    __nv_fp8_e4m3 f(v);
    return *reinterpret_cast<uint8_t*>(&f);
}

// Fused: blocks [0, XBLK) quantize x; blocks [XBLK, grid) cast w.
static constexpr int XBLK = 1024;
static constexpr int QBLOCKS = 1536;

__global__ void k_quant_xw(const float4* __restrict__ x, const float4* __restrict__ w,
                           int n4x, int n4w) {
    if (blockIdx.x < XBLK) {
        float amax = __uint_as_float(g_amax_bits);
        float s = fmaxf(amax, 1e-12f) / 448.0f;
        float r = 1.0f / s;
        uint32_t* __restrict__ A1 = reinterpret_cast<uint32_t*>(g_A);
        const int stride = XBLK * blockDim.x;
        for (int i = blockIdx.x * blockDim.x + threadIdx.x; i < n4x; i += stride) {
            float4 v = x[i];
            float q0 = fminf(fmaxf(div_rn(v.x, s, r), -448.f), 448.f);
            float q1 = fminf(fmaxf(div_rn(v.y, s, r), -448.f), 448.f);
            float q2 = fminf(fmaxf(div_rn(v.z, s, r), -448.f), 448.f);
            float q3 = fminf(fmaxf(div_rn(v.w, s, r), -448.f), 448.f);
            A1[i] = (uint32_t)e4m3_byte(q0) | ((uint32_t)e4m3_byte(q1) << 8) |
                    ((uint32_t)e4m3_byte(q2) << 16) | ((uint32_t)e4m3_byte(q3) << 24);
        }
    } else {
        uint32_t* __restrict__ B1 = reinterpret_cast<uint32_t*>(g_B);
        const int stride = (QBLOCKS - XBLK) * blockDim.x;
        for (int i = (blockIdx.x - XBLK) * blockDim.x + threadIdx.x; i < n4w; i += stride) {
            float4 v = w[i];
            B1[i] = (uint32_t)e4m3_byte(v.x) | ((uint32_t)e4m3_byte(v.y) << 8) |
                    ((uint32_t)e4m3_byte(v.z) << 16) | ((uint32_t)e4m3_byte(v.w) << 24);
        }
    }
}

// ---------------- GEMM (fp8 HMMA, 512 thr, BK=128/iter, 3-stage cp.async, 2 CTA/SM) ----
// Stage layout (A and B identical): 128 rows x 128 B.
// 16B chunk (row, kc 0..7): offset = row*128 + ((kc ^ (row&7)) << 4).
// Conflict-free for cp.async stores and every 8-lane ldmatrix phase.
__device__ __forceinline__ uint32_t sw_chunk(int row, int kc) {
    return (uint32_t)(row * 128 + ((kc ^ (row & 7)) << 4));
}

__global__ void __launch_bounds__(NTHREADS, 2)
fp8lin_gemm(const float* __restrict__ wscale, const float* __restrict__ bias,
            float* __restrict__ out) {
    extern __shared__ __align__(1024) char smem[];
    const uint32_t sbase = smem_u32(smem);
    const int tid = threadIdx.x;
    const int wid = tid >> 5;
    const int lane = tid & 31;
    const int wm = wid >> 2;          // 0..3  -> 32-row slab
    const int wn = wid & 3;           // 0..3  -> 32-col slab
    const int m0 = blockIdx.y * BM;
    const int n0 = blockIdx.x * BN;

    // per-thread cp.async invariants: 512 threads, 64B each per tile
    const int cp_row = tid >> 3;                       // 0..63
    const int cp_kc  = tid & 7;                        // fixed chunk column
    const uint32_t cp_dst = sw_chunk(cp_row, cp_kc);   // + j*64*128, j=0..1
    const char* Ag = reinterpret_cast<const char*>(g_A) + (size_t)(m0 + cp_row) * KDIM + cp_kc * 16;
    const char* Bg = reinterpret_cast<const char*>(g_B) + (size_t)(n0 + cp_row) * KDIM + cp_kc * 16;

    auto load_stage = [&](uint32_t sdst, int kblk) {
        const char* a = Ag + kblk * BK;
        const char* b = Bg + kblk * BK;
#pragma unroll
        for (int j = 0; j < 2; j++)
            cp16(sdst + cp_dst + j * (64 * 128), a + (size_t)j * 64 * KDIM);
#pragma unroll
        for (int j = 0; j < 2; j++)
            cp16(sdst + A_STAGE + cp_dst + j * (64 * 128), b + (size_t)j * 64 * KDIM);
    };

    // prologue: stages 0..1 in flight
#pragma unroll
    for (int s = 0; s < NSTAGE - 1; s++) {
        load_stage(sbase + s * STAGE_BYTES, s);
        cp_commit();
    }

    float acc[2][4][4];
#pragma unroll
    for (int i = 0; i < 2; i++)
#pragma unroll
        for (int j = 0; j < 4; j++)
#pragma unroll
            for (int q = 0; q < 4; q++) acc[i][j][q] = 0.f;

    // ldmatrix per-lane addressing (a "b16 col" is an fp8 byte-pair)
    const int a_rit = (lane & 7) + ((lane >> 3) & 1) * 8;  // A: row-in-tile 0..15
    const int a_kcs = (lane >> 4) & 1;                     // A: 16B-chunk select
    const int b_rit = (lane & 7) + ((lane >> 4) & 1) * 8;  // B: n-row
    const int b_kcs = (lane >> 3) & 1;                     // B: 16B-chunk select

    int bc = 0;            // buffer holding stage `it`
    int bl = NSTAGE - 1;   // buffer to receive stage `it + NSTAGE - 1`
    for (int it = 0; it < NIT; it++) {
        cp_wait1();          // stage `it` landed (<=1 group pending)
        __syncthreads();     // all warps done with iter it-1 (buffer bl is free)

        uint32_t sA = sbase + bc * STAGE_BYTES;
        uint32_t sB = sA + A_STAGE;

#pragma unroll
        for (int ks = 0; ks < 4; ks++) {     // each ks covers 32 fp8 k-bytes
            uint32_t ar[2][4], br[2][4];
#pragma unroll
            for (int i = 0; i < 2; i++) {
                int row = wm * 32 + i * 16 + a_rit;
                ldsm_x4(ar[i][0], ar[i][1], ar[i][2], ar[i][3],
                        sA + sw_chunk(row, 2 * ks + a_kcs));
            }
#pragma unroll
            for (int jj = 0; jj < 2; jj++) {
                int row = wn * 32 + jj * 16 + b_rit;
                ldsm_x4(br[jj][0], br[jj][1], br[jj][2], br[jj][3],
                        sB + sw_chunk(row, 2 * ks + b_kcs));
            }
            if (ks == 0) {   // prefetch issue overlaps the first mma block
                if (it + NSTAGE - 1 < NIT)
                    load_stage(sbase + bl * STAGE_BYTES, it + NSTAGE - 1);
                cp_commit();
            }
#pragma unroll
            for (int i = 0; i < 2; i++)
#pragma unroll
                for (int j = 0; j < 4; j++)
                    mma_fp8(acc[i][j], ar[i], br[j >> 1][(j & 1) * 2], br[j >> 1][(j & 1) * 2 + 1]);
        }

        if (++bc == NSTAGE) bc = 0;
        if (++bl == NSTAGE) bl = 0;
    }

    // epilogue: out = acc * (input_scale * weight_scale) + bias
    float amax = __uint_as_float(g_amax_bits);
    float mult = (fmaxf(amax, 1e-12f) / 448.0f) * wscale[0];

#pragma unroll
    for (int i = 0; i < 2; i++) {
        int row = m0 + wm * 32 + i * 16 + (lane >> 2);
#pragma unroll
        for (int j = 0; j < 4; j++) {
            int col = n0 + wn * 32 + j * 8 + (lane & 3) * 2;
            float2 bz = *reinterpret_cast<const float2*>(bias + col);
            float2 v0, v1;
            v0.x = fmaf(acc[i][j][0], mult, bz.x);
            v0.y = fmaf(acc[i][j][1], mult, bz.y);
            v1.x = fmaf(acc[i][j][2], mult, bz.x);
            v1.y = fmaf(acc[i][j][3], mult, bz.y);
            *reinterpret_cast<float2*>(out + (size_t)row * NDIM + col) = v0;
            *reinterpret_cast<float2*>(out + (size_t)(row + 8) * NDIM + col) = v1;
        }
    }
}

// ---------------- launch ----------------
extern "C" void kernel_launch(void* const* d_in, const int* in_sizes, int n_in,
                              void* d_out, int out_size) {
    const float* x    = (const float*)d_in[0];   // [4,2048,4096]
    const float* qw   = (const float*)d_in[1];   // [4096,4096]
    const float* ws   = (const float*)d_in[2];   // scalar
    const float* bias = (const float*)d_in[3];   // [4096]
    float* out = (float*)d_out;

    cudaFuncSetAttribute(fp8lin_gemm, cudaFuncAttributeMaxDynamicSharedMemorySize, SMEM_SIZE);

    k_reset<<<1, 1>>>();
    k_amax<<<1184, 256>>>((const float4*)x, (MDIM * KDIM) / 4);
    k_quant_xw<<<QBLOCKS, 256>>>((const float4*)x, (const float4*)qw,
                                 (MDIM * KDIM) / 4, (NDIM * KDIM) / 4);

    dim3 grid(NDIM / BN, MDIM / BM);  // 32 x 64 = 2048 CTAs
    fp8lin_gemm<<<grid, NTHREADS, SMEM_SIZE>>>(ws, bias, out);  // global launch idx 5 <- ncu
}

// round 9
// speedup vs baseline: 1.2286x; 1.2286x over previous
#include <cuda_runtime.h>
#include <cuda_bf16.h>
#include <cuda_fp8.h>
#include <cstdint>

// Shape (fixed): x[4,2048,4096] -> M=8192, K=4096; W[4096,4096] -> N=4096.
static constexpr int MDIM = 8192;
static constexpr int NDIM = 4096;
static constexpr int KDIM = 4096;

// fp8 tiles: BK = 128 fp8 bytes per mainloop iteration
static constexpr int BM = 128, BN = 128, BK = 128;
static constexpr int NSTAGE = 3;
static constexpr int A_STAGE = BM * BK;                // 16384 B
static constexpr int STAGE_BYTES = 2 * A_STAGE;        // 32768 B (A + B)
static constexpr int SMEM_SIZE = NSTAGE * STAGE_BYTES; // 96 KB -> 2 CTAs/SM (192KB)
static constexpr int NIT = KDIM / BK;                  // 32

// Scratch (allocation-free rule: __device__ globals)
__device__ uint8_t g_A[(size_t)MDIM * KDIM];   // 32 MB quantized activations (e4m3)
__device__ uint8_t g_B[(size_t)NDIM * KDIM];   // 16 MB quantized weights (e4m3)
__device__ unsigned g_amax_bits;

// ---------------- helpers ----------------
__device__ __forceinline__ uint32_t smem_u32(const void* p) {
    uint32_t a;
    asm("{ .reg .u64 t; cvta.to.shared.u64 t, %1; cvt.u32.u64 %0, t; }" : "=r"(a) : "l"(p));
    return a;
}
__device__ __forceinline__ void cp16(uint32_t dst, const void* src) {
    asm volatile("cp.async.cg.shared.global [%0], [%1], 16;" :: "r"(dst), "l"(src));
}
__device__ __forceinline__ void cp_commit() { asm volatile("cp.async.commit_group;" ::: "memory"); }
__device__ __forceinline__ void cp_wait1()  { asm volatile("cp.async.wait_group 1;" ::: "memory"); }

__device__ __forceinline__ void ldsm_x4(uint32_t& r0, uint32_t& r1, uint32_t& r2, uint32_t& r3,
                                        uint32_t addr) {
    asm volatile("ldmatrix.sync.aligned.m8n8.x4.shared.b16 {%0,%1,%2,%3}, [%4];"
                 : "=r"(r0), "=r"(r1), "=r"(r2), "=r"(r3) : "r"(addr));
}
// fp8 e4m3 MMA, fp32 accum, K=32 per instruction.
__device__ __forceinline__ void mma_fp8(float* c, const uint32_t* a, uint32_t b0, uint32_t b1) {
    asm volatile(
        "mma.sync.aligned.m16n8k32.row.col.f32.e4m3.e4m3.f32 "
        "{%0,%1,%2,%3}, {%4,%5,%6,%7}, {%8,%9}, {%0,%1,%2,%3};"
        : "+f"(c[0]), "+f"(c[1]), "+f"(c[2]), "+f"(c[3])
        : "r"(a[0]), "r"(a[1]), "r"(a[2]), "r"(a[3]), "r"(b0), "r"(b1));
}

// ---------------- quantization kernels ----------------
__global__ void k_reset() { g_amax_bits = 0u; }

__device__ __forceinline__ float max4(float4 v) {
    return fmaxf(fmaxf(fabsf(v.x), fabsf(v.y)), fmaxf(fabsf(v.z), fabsf(v.w)));
}

__global__ void k_amax(const float4* __restrict__ x, int n4) {
    const int stride = gridDim.x * blockDim.x;
    int i = blockIdx.x * blockDim.x + threadIdx.x;
    float m0 = 0.f, m1 = 0.f, m2 = 0.f, m3 = 0.f;
    for (; i + 3 * stride < n4; i += 4 * stride) {
        float4 a = x[i], b = x[i + stride], c = x[i + 2 * stride], d = x[i + 3 * stride];
        m0 = fmaxf(m0, max4(a));
        m1 = fmaxf(m1, max4(b));
        m2 = fmaxf(m2, max4(c));
        m3 = fmaxf(m3, max4(d));
    }
    for (; i < n4; i += stride) m0 = fmaxf(m0, max4(x[i]));
    float m = fmaxf(fmaxf(m0, m1), fmaxf(m2, m3));
#pragma unroll
    for (int o = 16; o; o >>= 1) m = fmaxf(m, __shfl_xor_sync(0xffffffffu, m, o));
    __shared__ float red[32];
    if ((threadIdx.x & 31) == 0) red[threadIdx.x >> 5] = m;
    __syncthreads();
    if (threadIdx.x < 32) {
        m = (threadIdx.x < (blockDim.x >> 5)) ? red[threadIdx.x] : 0.f;
#pragma unroll
        for (int o = 16; o; o >>= 1) m = fmaxf(m, __shfl_xor_sync(0xffffffffu, m, o));
        if (threadIdx.x == 0) atomicMax(&g_amax_bits, __float_as_uint(m));
    }
}

// Correctly-rounded x/s via one FMA refinement (matches reference's IEEE division)
__device__ __forceinline__ float div_rn(float x, float s, float r) {
    float q0 = x * r;
    return fmaf(fmaf(-s, q0, x), r, q0);
}
__device__ __forceinline__ uint8_t e4m3_byte(float v) {
    __nv_fp8_e4m3 f(v);
    return *reinterpret_cast<uint8_t*>(&f);
}

// Fused: blocks [0, XBLK) quantize x; blocks [XBLK, grid) cast w.
static constexpr int XBLK = 1024;
static constexpr int QBLOCKS = 1536;

__global__ void k_quant_xw(const float4* __restrict__ x, const float4* __restrict__ w,
                           int n4x, int n4w) {
    if (blockIdx.x < XBLK) {
        float amax = __uint_as_float(g_amax_bits);
        float s = fmaxf(amax, 1e-12f) / 448.0f;
        float r = 1.0f / s;
        uint32_t* __restrict__ A1 = reinterpret_cast<uint32_t*>(g_A);
        const int stride = XBLK * blockDim.x;
        for (int i = blockIdx.x * blockDim.x + threadIdx.x; i < n4x; i += stride) {
            float4 v = x[i];
            float q0 = fminf(fmaxf(div_rn(v.x, s, r), -448.f), 448.f);
            float q1 = fminf(fmaxf(div_rn(v.y, s, r), -448.f), 448.f);
            float q2 = fminf(fmaxf(div_rn(v.z, s, r), -448.f), 448.f);
            float q3 = fminf(fmaxf(div_rn(v.w, s, r), -448.f), 448.f);
            A1[i] = (uint32_t)e4m3_byte(q0) | ((uint32_t)e4m3_byte(q1) << 8) |
                    ((uint32_t)e4m3_byte(q2) << 16) | ((uint32_t)e4m3_byte(q3) << 24);
        }
    } else {
        uint32_t* __restrict__ B1 = reinterpret_cast<uint32_t*>(g_B);
        const int stride = (QBLOCKS - XBLK) * blockDim.x;
        for (int i = (blockIdx.x - XBLK) * blockDim.x + threadIdx.x; i < n4w; i += stride) {
            float4 v = w[i];
            B1[i] = (uint32_t)e4m3_byte(v.x) | ((uint32_t)e4m3_byte(v.y) << 8) |
                    ((uint32_t)e4m3_byte(v.z) << 16) | ((uint32_t)e4m3_byte(v.w) << 24);
        }
    }
}

// ---------------- GEMM (fp8 HMMA, 256 thr, BK=128/iter, 3-stage cp.async, 2 CTA/SM) ----
// Stage layout (A and B identical): 128 rows x 128 B.
// 16B chunk (row, kc 0..7): offset = row*128 + ((kc ^ (row&7)) << 4).
// Identity: kc = 2*ks + kcs, kcs in {0,1}, disjoint bits =>
//   offset(row, 2ks+kcs) = offset(row, kcs) ^ (ks << 5)
// so the 6 per-warp ldsm offsets are loop-invariant; per ldsm = one XOR-imm.
__device__ __forceinline__ uint32_t sw_chunk(int row, int kc) {
    return (uint32_t)(row * 128 + ((kc ^ (row & 7)) << 4));
}

__global__ void __launch_bounds__(256, 2)
fp8lin_gemm(const float* __restrict__ wscale, const float* __restrict__ bias,
            float* __restrict__ out) {
    extern __shared__ __align__(1024) char smem[];
    const uint32_t sbase = smem_u32(smem);
    const int tid = threadIdx.x;
    const int wid = tid >> 5;
    const int lane = tid & 31;
    const int wm = wid >> 2;          // 0..1  -> 64-row slab
    const int wn = wid & 3;           // 0..3  -> 32-col slab
    const int m0 = blockIdx.y * BM;
    const int n0 = blockIdx.x * BN;

    // per-thread cp.async invariants
    const int cp_row = tid >> 3;                       // 0..31
    const int cp_kc  = tid & 7;                        // fixed chunk column
    const uint32_t cp_dst = sw_chunk(cp_row, cp_kc);   // + j*32*128, j=0..3
    const char* Ag = reinterpret_cast<const char*>(g_A) + (size_t)(m0 + cp_row) * KDIM + cp_kc * 16;
    const char* Bg = reinterpret_cast<const char*>(g_B) + (size_t)(n0 + cp_row) * KDIM + cp_kc * 16;

    auto load_stage = [&](uint32_t sdst, int kblk) {
        const char* a = Ag + kblk * BK;
        const char* b = Bg + kblk * BK;
#pragma unroll
        for (int j = 0; j < 4; j++)
            cp16(sdst + cp_dst + j * (32 * 128), a + (size_t)j * 32 * KDIM);
#pragma unroll
        for (int j = 0; j < 4; j++)
            cp16(sdst + A_STAGE + cp_dst + j * (32 * 128), b + (size_t)j * 32 * KDIM);
    };

    // prologue: stages 0..1 in flight
#pragma unroll
    for (int s = 0; s < NSTAGE - 1; s++) {
        load_stage(sbase + s * STAGE_BYTES, s);
        cp_commit();
    }

    float acc[4][4][4];
#pragma unroll
    for (int i = 0; i < 4; i++)
#pragma unroll
        for (int j = 0; j < 4; j++)
#pragma unroll
            for (int q = 0; q < 4; q++) acc[i][j][q] = 0.f;

    // 6 loop-invariant ldsm offsets (ks enters only via XOR (ks<<5))
    const int a_rit = (lane & 7) + ((lane >> 3) & 1) * 8;
    const int a_kcs = (lane >> 4) & 1;
    const int b_rit = (lane & 7) + ((lane >> 4) & 1) * 8;
    const int b_kcs = (lane >> 3) & 1;
    uint32_t offA[4], offB[2];
#pragma unroll
    for (int i = 0; i < 4; i++)
        offA[i] = sw_chunk(wm * 64 + i * 16 + a_rit, a_kcs);
#pragma unroll
    for (int jj = 0; jj < 2; jj++)
        offB[jj] = (uint32_t)A_STAGE + sw_chunk(wn * 32 + jj * 16 + b_rit, b_kcs);

    int bc = 0;            // buffer holding stage `it`
    int bl = NSTAGE - 1;   // buffer to receive stage `it + NSTAGE - 1`
    for (int it = 0; it < NIT; it++) {
        cp_wait1();          // stage `it` landed (<=1 group pending)
        __syncthreads();     // all warps done with iter it-1 (buffer bl is free)

        const uint32_t sA = sbase + bc * STAGE_BYTES;
        uint32_t baseA[4], baseB[2];
#pragma unroll
        for (int i = 0; i < 4; i++) baseA[i] = sA + offA[i];
#pragma unroll
        for (int jj = 0; jj < 2; jj++) baseB[jj] = sA + offB[jj];

#pragma unroll
        for (int ks = 0; ks < 4; ks++) {     // each ks covers 32 fp8 k-bytes
            uint32_t ar[4][4], br[2][4];
#pragma unroll
            for (int i = 0; i < 4; i++)
                ldsm_x4(ar[i][0], ar[i][1], ar[i][2], ar[i][3],
                        baseA[i] ^ (uint32_t)(ks << 5));
#pragma unroll
            for (int jj = 0; jj < 2; jj++)
                ldsm_x4(br[jj][0], br[jj][1], br[jj][2], br[jj][3],
                        baseB[jj] ^ (uint32_t)(ks << 5));
            if (ks == 0) {   // prefetch issue overlaps the first mma block
                if (it + NSTAGE - 1 < NIT)
                    load_stage(sbase + bl * STAGE_BYTES, it + NSTAGE - 1);
                cp_commit();
            }
#pragma unroll
            for (int i = 0; i < 4; i++)
#pragma unroll
                for (int j = 0; j < 4; j++)
                    mma_fp8(acc[i][j], ar[i], br[j >> 1][(j & 1) * 2], br[j >> 1][(j & 1) * 2 + 1]);
        }

        if (++bc == NSTAGE) bc = 0;
        if (++bl == NSTAGE) bl = 0;
    }

    // epilogue: out = acc * (input_scale * weight_scale) + bias
    float amax = __uint_as_float(g_amax_bits);
    float mult = (fmaxf(amax, 1e-12f) / 448.0f) * wscale[0];

#pragma unroll
    for (int i = 0; i < 4; i++) {
        int row = m0 + wm * 64 + i * 16 + (lane >> 2);
#pragma unroll
        for (int j = 0; j < 4; j++) {
            int col = n0 + wn * 32 + j * 8 + (lane & 3) * 2;
            float2 bz = *reinterpret_cast<const float2*>(bias + col);
            float2 v0, v1;
            v0.x = fmaf(acc[i][j][0], mult, bz.x);
            v0.y = fmaf(acc[i][j][1], mult, bz.y);
            v1.x = fmaf(acc[i][j][2], mult, bz.x);
            v1.y = fmaf(acc[i][j][3], mult, bz.y);
            *reinterpret_cast<float2*>(out + (size_t)row * NDIM + col) = v0;
            *reinterpret_cast<float2*>(out + (size_t)(row + 8) * NDIM + col) = v1;
        }
    }
}

// ---------------- launch ----------------
extern "C" void kernel_launch(void* const* d_in, const int* in_sizes, int n_in,
                              void* d_out, int out_size) {
    const float* x    = (const float*)d_in[0];   // [4,2048,4096]
    const float* qw   = (const float*)d_in[1];   // [4096,4096]
    const float* ws   = (const float*)d_in[2];   // scalar
    const float* bias = (const float*)d_in[3];   // [4096]
    float* out = (float*)d_out;

    cudaFuncSetAttribute(fp8lin_gemm, cudaFuncAttributeMaxDynamicSharedMemorySize, SMEM_SIZE);

    k_reset<<<1, 1>>>();
    k_amax<<<1184, 256>>>((const float4*)x, (MDIM * KDIM) / 4);
    k_quant_xw<<<QBLOCKS, 256>>>((const float4*)x, (const float4*)qw,
                                 (MDIM * KDIM) / 4, (NDIM * KDIM) / 4);

    dim3 grid(NDIM / BN, MDIM / BM);  // 32 x 64 = 2048 CTAs
    fp8lin_gemm<<<grid, 256, SMEM_SIZE>>>(ws, bias, out);  // global launch idx 5 <- ncu
}